// round 1
// baseline (speedup 1.0000x reference)
#include <cuda_runtime.h>
#include <math.h>
#include <stdint.h>

#define NPTS 200000
#define TVSEG 1382400           // B*GZ2*GY2*GX2 = 2*16*180*240
#define NSEG_TOTAL 1634400      // 1382400 + 172800 + 57600 + 21600

// ---------------- scratch (device globals; no allocation allowed) ----------
__device__ float g_reduced[NPTS * 64];                  // 51.2 MB
__device__ float g_segsum[(size_t)NSEG_TOTAL * 64];     // 418 MB
__device__ float g_segcnt[NSEG_TOTAL];                  // 6.5 MB
__device__ int   g_lin[NPTS * 4];
__device__ float g_proj[NPTS * 64];                     // pre-gather proj

// ---------------- K1: reduced = relu(X@W_red + b) + segment scatter --------
__global__ void __launch_bounds__(256) k1_reduce(
    const float* __restrict__ input, const int* __restrict__ coords,
    const float* __restrict__ W_red, const float* __restrict__ b_red)
{
    __shared__ float sW[64 * 64];
    __shared__ float sb[64];
    for (int i = threadIdx.x; i < 64 * 64; i += 256) sW[i] = W_red[i];
    if (threadIdx.x < 64) sb[threadIdx.x] = b_red[threadIdx.x];
    __syncthreads();

    const int lane = threadIdx.x & 31;
    int warp = (blockIdx.x * 256 + threadIdx.x) >> 5;
    const int nwarp = (gridDim.x * 256) >> 5;

    const int PS[4]  = {2, 4, 6, 8};
    const int DX[4]  = {240, 120, 80, 60};
    const int DY[4]  = {180, 90, 60, 45};
    const int DZ[4]  = {16, 8, 6, 4};
    const int OFF[4] = {0, 1382400, 1555200, 1612800};

    for (int n = warp; n < NPTS; n += nwarp) {
        float2 x2 = reinterpret_cast<const float2*>(input)[n * 32 + lane];
        float a0 = sb[lane], a1 = sb[lane + 32];
        #pragma unroll
        for (int k = 0; k < 64; ++k) {
            float xk = __shfl_sync(0xffffffffu, (k & 1) ? x2.y : x2.x, k >> 1);
            a0 = fmaf(xk, sW[k * 64 + lane], a0);
            a1 = fmaf(xk, sW[k * 64 + lane + 32], a1);
        }
        a0 = fmaxf(a0, 0.f); a1 = fmaxf(a1, 0.f);
        g_reduced[n * 64 + lane]      = a0;
        g_reduced[n * 64 + lane + 32] = a1;

        int4 c = reinterpret_cast<const int4*>(coords)[n];
        #pragma unroll
        for (int j = 0; j < 4; ++j) {
            int qx = c.y / PS[j], qy = c.z / PS[j], qz = c.w / PS[j];
            int lin = ((c.x * DX[j] + qx) * DY[j] + qy) * DZ[j] + qz + OFF[j];
            size_t base = (size_t)lin * 64;
            atomicAdd(&g_segsum[base + lane], a0);
            atomicAdd(&g_segsum[base + lane + 32], a1);
            if (lane == 0) {
                g_lin[n * 4 + j] = lin;
                atomicAdd(&g_segcnt[lin], 1.0f);
            }
        }
    }
}

// ---------------- K2: per-point MLP chain (warp per point, SMEM weights) ---
// dynamic smem layout (floats):
//  flW 0..8192 | flb 8192..8320 | fcW 8320..9344 | fcsW 9344..13440 |
//  fcsb 13440..13568 | outW 13568..15616 | lo1 15616..23808 |
//  lo2 23808..27904 | lob 27904..27968      => 27968 floats = 111872 B
#define K2_SMEM_BYTES (27968 * 4)

__global__ void __launch_bounds__(256) k2_point(
    const float* __restrict__ fc_list_W, const float* __restrict__ fc_list_b,
    const float* __restrict__ fcs_W, const float* __restrict__ fcs_b,
    const float* __restrict__ fc_W, const float* __restrict__ out_fc_W,
    const float* __restrict__ lo_W1, const float* __restrict__ lo_W2,
    const float* __restrict__ lo_b2)
{
    extern __shared__ float sm[];
    float* s_flW  = sm;
    float* s_flb  = sm + 8192;
    float* s_fcW  = sm + 8320;
    float* s_fcsW = sm + 9344;
    float* s_fcsb = sm + 13440;
    float* s_outW = sm + 13568;
    float* s_lo1  = sm + 15616;
    float* s_lo2  = sm + 23808;
    float* s_lob  = sm + 27904;

    for (int i = threadIdx.x; i < 8192; i += 256) s_flW[i]  = fc_list_W[i];
    for (int i = threadIdx.x; i < 128;  i += 256) s_flb[i]  = fc_list_b[i];
    for (int i = threadIdx.x; i < 1024; i += 256) s_fcW[i]  = fc_W[i];
    for (int i = threadIdx.x; i < 4096; i += 256) s_fcsW[i] = fcs_W[i];
    for (int i = threadIdx.x; i < 128;  i += 256) s_fcsb[i] = fcs_b[i];
    for (int i = threadIdx.x; i < 2048; i += 256) s_outW[i] = out_fc_W[i];
    for (int i = threadIdx.x; i < 8192; i += 256) s_lo1[i]  = lo_W1[i];
    for (int i = threadIdx.x; i < 4096; i += 256) s_lo2[i]  = lo_W2[i];
    if (threadIdx.x < 64) s_lob[threadIdx.x] = lo_b2[threadIdx.x];
    __syncthreads();

    const int lane = threadIdx.x & 31;
    int warp = (blockIdx.x * 256 + threadIdx.x) >> 5;
    const int nwarp = (gridDim.x * 256) >> 5;

    for (int n = warp; n < NPTS; n += nwarp) {
        float sf[4];
        float featS = 0.f;

        // per-scale: fkm = segsum/cnt, att_j = relu(fkm @ fc_list_W[j] + b_j)
        #pragma unroll
        for (int j = 0; j < 4; ++j) {
            int lin = g_lin[n * 4 + j];
            float inv = 1.f / fmaxf(g_segcnt[lin], 1.f);
            float2 s2 = reinterpret_cast<const float2*>(g_segsum)[(size_t)lin * 32 + lane];
            float f0 = s2.x * inv, f1 = s2.y * inv;
            float acc = s_flb[j * 32 + lane];
            #pragma unroll
            for (int k = 0; k < 64; ++k) {
                float xk = __shfl_sync(0xffffffffu, (k & 1) ? f1 : f0, k >> 1);
                acc = fmaf(xk, s_flW[(j * 64 + k) * 32 + lane], acc);
            }
            sf[j] = fmaxf(acc, 0.f);
            featS += sf[j];
        }

        // feat_Z = relu(feat_S @ fc_W)
        float z = 0.f;
        #pragma unroll
        for (int k = 0; k < 32; ++k)
            z = fmaf(__shfl_sync(0xffffffffu, featS, k), s_fcW[k * 32 + lane], z);
        z = fmaxf(z, 0.f);

        // att_v = sigmoid(feat_Z @ fcs_W[j] + b); fused_pre = sum_j sf_j*att_v_j
        float fp = 0.f;
        #pragma unroll
        for (int j = 0; j < 4; ++j) {
            float acc = s_fcsb[j * 32 + lane];
            #pragma unroll
            for (int k = 0; k < 32; ++k)
                acc = fmaf(__shfl_sync(0xffffffffu, z, k), s_fcsW[(j * 32 + k) * 32 + lane], acc);
            float av = 1.f / (1.f + __expf(-acc));
            fp = fmaf(sf[j], av, fp);
        }

        // fused = fused_pre @ out_fc_W  (-> 64 channels, 2 per lane)
        float f0 = 0.f, f1 = 0.f;
        #pragma unroll
        for (int k = 0; k < 32; ++k) {
            float fk = __shfl_sync(0xffffffffu, fp, k);
            f0 = fmaf(fk, s_outW[k * 64 + lane], f0);
            f1 = fmaf(fk, s_outW[k * 64 + lane + 32], f1);
        }

        // h = relu([reduced, fused] @ lo_W1)
        float2 r2 = reinterpret_cast<const float2*>(g_reduced)[n * 32 + lane];
        float h0 = 0.f, h1 = 0.f;
        #pragma unroll
        for (int k = 0; k < 64; ++k) {
            float xk = __shfl_sync(0xffffffffu, (k & 1) ? r2.y : r2.x, k >> 1);
            h0 = fmaf(xk, s_lo1[k * 64 + lane], h0);
            h1 = fmaf(xk, s_lo1[k * 64 + lane + 32], h1);
        }
        #pragma unroll
        for (int k = 0; k < 32; ++k) {
            float xk = __shfl_sync(0xffffffffu, f0, k);
            h0 = fmaf(xk, s_lo1[(64 + k) * 64 + lane], h0);
            h1 = fmaf(xk, s_lo1[(64 + k) * 64 + lane + 32], h1);
        }
        #pragma unroll
        for (int k = 0; k < 32; ++k) {
            float xk = __shfl_sync(0xffffffffu, f1, k);
            h0 = fmaf(xk, s_lo1[(96 + k) * 64 + lane], h0);
            h1 = fmaf(xk, s_lo1[(96 + k) * 64 + lane + 32], h1);
        }
        h0 = fmaxf(h0, 0.f); h1 = fmaxf(h1, 0.f);

        // proj = h @ lo_W2 + lo_b2
        float p0 = s_lob[lane], p1 = s_lob[lane + 32];
        #pragma unroll
        for (int k = 0; k < 32; ++k) {
            float hk = __shfl_sync(0xffffffffu, h0, k);
            p0 = fmaf(hk, s_lo2[k * 64 + lane], p0);
            p1 = fmaf(hk, s_lo2[k * 64 + lane + 32], p1);
        }
        #pragma unroll
        for (int k = 0; k < 32; ++k) {
            float hk = __shfl_sync(0xffffffffu, h1, k);
            p0 = fmaf(hk, s_lo2[(32 + k) * 64 + lane], p0);
            p1 = fmaf(hk, s_lo2[(32 + k) * 64 + lane + 32], p1);
        }
        g_proj[n * 64 + lane]      = p0;
        g_proj[n * 64 + lane + 32] = p1;
    }
}

// ---------------- K3: gather by inv + segment-max scatter + lin2 out -------
__device__ __forceinline__ void atomicMaxFloat(float* addr, float v)
{
    if (v >= 0.f) atomicMax((int*)addr, __float_as_int(v));
    else          atomicMin((unsigned int*)addr, __float_as_uint(v));
}

__global__ void __launch_bounds__(256) k3_scatter(
    const int* __restrict__ inv, const int* __restrict__ bxyz,
    float* __restrict__ out)
{
    int idx = blockIdx.x * 256 + threadIdx.x;
    if (idx >= NPTS * 64) return;
    int n = idx >> 6, c = idx & 63;
    int src = inv[n];
    float v = g_proj[src * 64 + c];
    out[idx] = v;

    int4 bz = reinterpret_cast<const int4*>(bxyz)[n];
    // lin2 = ((b*GZ2 + z)*GY2 + y)*GX2 + x   (cols: b,x,y,z)
    int lin2 = ((bz.x * 16 + bz.w) * 180 + bz.z) * 240 + bz.y;
    float* tv = out + (size_t)NPTS * 64;
    atomicMaxFloat(&tv[(size_t)lin2 * 64 + c], v);
    if (c == 0)
        out[(size_t)NPTS * 64 + (size_t)TVSEG * 64 + n] = (float)lin2;
}

// ---------------- K4: untouched (0xFFFFFFFF init pattern) -> 0.0 -----------
__global__ void __launch_bounds__(256) k4_final(float* __restrict__ tv)
{
    size_t idx = (size_t)blockIdx.x * 256 + threadIdx.x;   // float4 units
    if (idx >= (size_t)TVSEG * 16) return;
    uint4 v = reinterpret_cast<uint4*>(tv)[idx];
    bool ch = false;
    if (v.x == 0xFFFFFFFFu) { v.x = 0u; ch = true; }
    if (v.y == 0xFFFFFFFFu) { v.y = 0u; ch = true; }
    if (v.z == 0xFFFFFFFFu) { v.z = 0u; ch = true; }
    if (v.w == 0xFFFFFFFFu) { v.w = 0u; ch = true; }
    if (ch) reinterpret_cast<uint4*>(tv)[idx] = v;
}

// ---------------- launch ---------------------------------------------------
extern "C" void kernel_launch(void* const* d_in, const int* in_sizes, int n_in,
                              void* d_out, int out_size)
{
    const float* input     = (const float*)d_in[0];
    const int*   coords    = (const int*)  d_in[1];
    const int*   inv       = (const int*)  d_in[2];
    const int*   bxyz      = (const int*)  d_in[3];
    const float* W_red     = (const float*)d_in[4];
    const float* b_red     = (const float*)d_in[5];
    const float* fc_list_W = (const float*)d_in[6];
    const float* fc_list_b = (const float*)d_in[7];
    const float* fcs_W     = (const float*)d_in[8];
    const float* fcs_b     = (const float*)d_in[9];
    const float* fc_W      = (const float*)d_in[10];
    const float* out_fc_W  = (const float*)d_in[11];
    const float* lo_W1     = (const float*)d_in[12];
    const float* lo_W2     = (const float*)d_in[13];
    const float* lo_b2     = (const float*)d_in[14];
    float* out = (float*)d_out;

    void* p;
    cudaGetSymbolAddress(&p, g_segsum);
    cudaMemsetAsync(p, 0, (size_t)NSEG_TOTAL * 64 * sizeof(float));
    cudaGetSymbolAddress(&p, g_segcnt);
    cudaMemsetAsync(p, 0, (size_t)NSEG_TOTAL * sizeof(float));
    // tv region init pattern: 0xFFFFFFFF (acts as -inf sentinel for atomic max)
    cudaMemsetAsync(out + (size_t)NPTS * 64, 0xFF, (size_t)TVSEG * 64 * sizeof(float));

    cudaFuncSetAttribute(k2_point, cudaFuncAttributeMaxDynamicSharedMemorySize,
                         K2_SMEM_BYTES);

    k1_reduce<<<1184, 256>>>(input, coords, W_red, b_red);
    k2_point<<<296, 256, K2_SMEM_BYTES>>>(fc_list_W, fc_list_b, fcs_W, fcs_b,
                                          fc_W, out_fc_W, lo_W1, lo_W2, lo_b2);
    k3_scatter<<<(NPTS * 64 + 255) / 256, 256>>>(inv, bxyz, out);
    k4_final<<<((size_t)TVSEG * 16 + 255) / 256, 256>>>(out + (size_t)NPTS * 64);
}

// round 2
// speedup vs baseline: 1.5451x; 1.5451x over previous
#include <cuda_runtime.h>
#include <math.h>
#include <stdint.h>

#define NPTS 200000
#define TVSEG 1382400           // B*GZ2*GY2*GX2 = 2*16*180*240
#define NSEG_TOTAL 1634400      // 1382400 + 172800 + 57600 + 21600

// ---------------- scratch (device globals; no allocation allowed) ----------
__device__ float g_reduced[NPTS * 64];                  // 51 MB
__device__ float g_segsum[(size_t)NSEG_TOTAL * 64];     // 418 MB (touched-only init)
__device__ float g_segcnt[NSEG_TOTAL];
__device__ int   g_lin[NPTS * 4];
__device__ float g_sf[(size_t)NPTS * 128];              // 102 MB spill
__device__ float g_z[(size_t)NPTS * 32];                // 26 MB spill
__device__ float g_proj[NPTS * 64];
__device__ float g_tv[(size_t)TVSEG * 64];              // 354 MB (touched-only init)
__device__ int   g_lin2[NPTS];
__device__ unsigned char g_flag[TVSEG];

// ---------------- k0: zero touched segments + compute lin ------------------
__global__ void __launch_bounds__(256) k0_zero(const int* __restrict__ coords)
{
    int w = (blockIdx.x * 256 + threadIdx.x) >> 5;   // point
    int lane = threadIdx.x & 31;
    int j  = lane >> 3;          // scale 0..3
    int c8 = lane & 7;           // chunk 0..7

    int4 c = reinterpret_cast<const int4*>(coords)[w];
    int ps = (j == 0) ? 2 : (j == 1) ? 4 : (j == 2) ? 6 : 8;
    int dx = (j == 0) ? 240 : (j == 1) ? 120 : (j == 2) ? 80 : 60;
    int dy = (j == 0) ? 180 : (j == 1) ? 90 : (j == 2) ? 60 : 45;
    int dz = (j == 0) ? 16 : (j == 1) ? 8 : (j == 2) ? 6 : 4;
    int off = (j == 0) ? 0 : (j == 1) ? 1382400 : (j == 2) ? 1555200 : 1612800;

    int lin = ((c.x * dx + c.y / ps) * dy + c.z / ps) * dz + c.w / ps + off;
    if (c8 == 0) {
        g_lin[w * 4 + j] = lin;
        g_segcnt[lin] = 0.f;
    }
    float4 z4 = make_float4(0.f, 0.f, 0.f, 0.f);
    float4* dst = reinterpret_cast<float4*>(g_segsum + (size_t)lin * 64) + c8 * 2;
    dst[0] = z4;
    dst[1] = z4;
}

// ---------------- k1: reduced = relu(X@W_red + b) + atomic segment scatter -
__global__ void __launch_bounds__(256) k1_reduce(
    const float* __restrict__ input,
    const float* __restrict__ W_red, const float* __restrict__ b_red)
{
    __shared__ float sW[64 * 64];
    __shared__ float sb[64];
    for (int i = threadIdx.x; i < 64 * 64; i += 256) sW[i] = W_red[i];
    if (threadIdx.x < 64) sb[threadIdx.x] = b_red[threadIdx.x];
    __syncthreads();

    const int lane = threadIdx.x & 31;
    int w = (blockIdx.x * 256 + threadIdx.x) >> 5;

    // lane owns channels 2*lane, 2*lane+1
    float2 x2 = reinterpret_cast<const float2*>(input)[w * 32 + lane];
    float a0 = sb[2 * lane], a1 = sb[2 * lane + 1];
    #pragma unroll
    for (int k = 0; k < 64; ++k) {
        float xk = __shfl_sync(0xffffffffu, (k & 1) ? x2.y : x2.x, k >> 1);
        float2 w2 = reinterpret_cast<const float2*>(sW)[k * 32 + lane];
        a0 = fmaf(xk, w2.x, a0);
        a1 = fmaf(xk, w2.y, a1);
    }
    a0 = fmaxf(a0, 0.f); a1 = fmaxf(a1, 0.f);
    reinterpret_cast<float2*>(g_reduced)[w * 32 + lane] = make_float2(a0, a1);

    #pragma unroll
    for (int j = 0; j < 4; ++j) {
        int lin = g_lin[w * 4 + j];
        float* addr = g_segsum + (size_t)lin * 64 + 2 * lane;
        asm volatile("red.global.add.v2.f32 [%0], {%1, %2};"
                     :: "l"(addr), "f"(a0), "f"(a1) : "memory");
        if (lane == 0) atomicAdd(&g_segcnt[lin], 1.0f);
    }
}

// ---------------- k2a: per-point (thread) stage1 + featS + z ---------------
// smem floats: flW 8192 | flb 128 | fcW 1024 | scratch 16384  = 25728
#define K2A_SMEM (25728 * 4)
__global__ void __launch_bounds__(256) k2a_point(
    const float* __restrict__ flW, const float* __restrict__ flb,
    const float* __restrict__ fcW)
{
    extern __shared__ float sm[];
    float* s_flW = sm;
    float* s_flb = sm + 8192;
    float* s_fcW = sm + 8320;
    float* s_x   = sm + 9344;

    for (int i = threadIdx.x; i < 8192; i += 256) s_flW[i] = flW[i];
    for (int i = threadIdx.x; i < 128;  i += 256) s_flb[i] = flb[i];
    for (int i = threadIdx.x; i < 1024; i += 256) s_fcW[i] = fcW[i];
    __syncthreads();

    int n = blockIdx.x * 256 + threadIdx.x;
    if (n >= NPTS) return;
    const int tid = threadIdx.x;

    float featS[32];
    #pragma unroll
    for (int c = 0; c < 32; ++c) featS[c] = 0.f;

    #pragma unroll 1
    for (int j = 0; j < 4; ++j) {
        int lin = g_lin[n * 4 + j];
        float inv = 1.f / fmaxf(g_segcnt[lin], 1.f);
        const float4* fk4 = reinterpret_cast<const float4*>(g_segsum + (size_t)lin * 64);
        float4 fk[16];
        #pragma unroll
        for (int i = 0; i < 16; ++i) fk[i] = fk4[i];

        float acc[32];
        #pragma unroll
        for (int c = 0; c < 32; ++c) acc[c] = s_flb[j * 32 + c];

        #pragma unroll
        for (int k4 = 0; k4 < 16; ++k4) {
            #pragma unroll
            for (int kk = 0; kk < 4; ++kk) {
                float xk = ((kk == 0) ? fk[k4].x : (kk == 1) ? fk[k4].y
                            : (kk == 2) ? fk[k4].z : fk[k4].w) * inv;
                #pragma unroll
                for (int c4 = 0; c4 < 8; ++c4) {
                    float4 wv = reinterpret_cast<const float4*>(s_flW)
                                    [(j * 64 + k4 * 4 + kk) * 8 + c4];
                    acc[c4 * 4 + 0] = fmaf(xk, wv.x, acc[c4 * 4 + 0]);
                    acc[c4 * 4 + 1] = fmaf(xk, wv.y, acc[c4 * 4 + 1]);
                    acc[c4 * 4 + 2] = fmaf(xk, wv.z, acc[c4 * 4 + 2]);
                    acc[c4 * 4 + 3] = fmaf(xk, wv.w, acc[c4 * 4 + 3]);
                }
            }
        }
        float4* sfdst = reinterpret_cast<float4*>(g_sf + (size_t)n * 128 + j * 32);
        #pragma unroll
        for (int c4 = 0; c4 < 8; ++c4) {
            float4 v;
            v.x = fmaxf(acc[c4 * 4 + 0], 0.f);
            v.y = fmaxf(acc[c4 * 4 + 1], 0.f);
            v.z = fmaxf(acc[c4 * 4 + 2], 0.f);
            v.w = fmaxf(acc[c4 * 4 + 3], 0.f);
            sfdst[c4] = v;
            featS[c4 * 4 + 0] += v.x;
            featS[c4 * 4 + 1] += v.y;
            featS[c4 * 4 + 2] += v.z;
            featS[c4 * 4 + 3] += v.w;
        }
    }

    // featS -> scratch; z = relu(featS @ fc_W)
    #pragma unroll
    for (int c = 0; c < 32; ++c) s_x[c * 256 + tid] = featS[c];
    float z[32];
    #pragma unroll
    for (int c = 0; c < 32; ++c) z[c] = 0.f;
    #pragma unroll 1
    for (int k = 0; k < 32; ++k) {
        float fS = s_x[k * 256 + tid];
        #pragma unroll
        for (int c4 = 0; c4 < 8; ++c4) {
            float4 wv = reinterpret_cast<const float4*>(s_fcW)[k * 8 + c4];
            z[c4 * 4 + 0] = fmaf(fS, wv.x, z[c4 * 4 + 0]);
            z[c4 * 4 + 1] = fmaf(fS, wv.y, z[c4 * 4 + 1]);
            z[c4 * 4 + 2] = fmaf(fS, wv.z, z[c4 * 4 + 2]);
            z[c4 * 4 + 3] = fmaf(fS, wv.w, z[c4 * 4 + 3]);
        }
    }
    float4* zdst = reinterpret_cast<float4*>(g_z + (size_t)n * 32);
    #pragma unroll
    for (int c4 = 0; c4 < 8; ++c4) {
        float4 v;
        v.x = fmaxf(z[c4 * 4 + 0], 0.f);
        v.y = fmaxf(z[c4 * 4 + 1], 0.f);
        v.z = fmaxf(z[c4 * 4 + 2], 0.f);
        v.w = fmaxf(z[c4 * 4 + 3], 0.f);
        zdst[c4] = v;
    }
}

// ---------------- k2b: attention fuse + lo MLP + proj ----------------------
// smem floats: fcsW 4096 | fcsb 128 | outW 2048 | lo1 8192 | lo2 4096 | lob 64
//              | scratch 16384 = 35008
#define K2B_SMEM (35008 * 4)
__global__ void __launch_bounds__(256) k2b_point(
    const float* __restrict__ fcsW, const float* __restrict__ fcsb,
    const float* __restrict__ outW, const float* __restrict__ lo1,
    const float* __restrict__ lo2, const float* __restrict__ lob)
{
    extern __shared__ float sm[];
    float* s_fcsW = sm;
    float* s_fcsb = sm + 4096;
    float* s_outW = sm + 4224;
    float* s_lo1  = sm + 6272;
    float* s_lo2  = sm + 14464;
    float* s_lob  = sm + 18560;
    float* s_x    = sm + 18624;

    for (int i = threadIdx.x; i < 4096; i += 256) s_fcsW[i] = fcsW[i];
    for (int i = threadIdx.x; i < 128;  i += 256) s_fcsb[i] = fcsb[i];
    for (int i = threadIdx.x; i < 2048; i += 256) s_outW[i] = outW[i];
    for (int i = threadIdx.x; i < 8192; i += 256) s_lo1[i]  = lo1[i];
    for (int i = threadIdx.x; i < 4096; i += 256) s_lo2[i]  = lo2[i];
    if (threadIdx.x < 64) s_lob[threadIdx.x] = lob[threadIdx.x];
    __syncthreads();

    int n = blockIdx.x * 256 + threadIdx.x;
    if (n >= NPTS) return;
    const int tid = threadIdx.x;

    // z -> scratch
    {
        const float4* zsrc = reinterpret_cast<const float4*>(g_z + (size_t)n * 32);
        #pragma unroll
        for (int c4 = 0; c4 < 8; ++c4) {
            float4 v = zsrc[c4];
            s_x[(c4 * 4 + 0) * 256 + tid] = v.x;
            s_x[(c4 * 4 + 1) * 256 + tid] = v.y;
            s_x[(c4 * 4 + 2) * 256 + tid] = v.z;
            s_x[(c4 * 4 + 3) * 256 + tid] = v.w;
        }
    }

    float fp[32];
    #pragma unroll
    for (int c = 0; c < 32; ++c) fp[c] = 0.f;

    #pragma unroll 1
    for (int j = 0; j < 4; ++j) {
        float acc[32];
        #pragma unroll
        for (int c = 0; c < 32; ++c) acc[c] = s_fcsb[j * 32 + c];
        #pragma unroll 1
        for (int k = 0; k < 32; ++k) {
            float zk = s_x[k * 256 + tid];
            #pragma unroll
            for (int c4 = 0; c4 < 8; ++c4) {
                float4 wv = reinterpret_cast<const float4*>(s_fcsW)[(j * 32 + k) * 8 + c4];
                acc[c4 * 4 + 0] = fmaf(zk, wv.x, acc[c4 * 4 + 0]);
                acc[c4 * 4 + 1] = fmaf(zk, wv.y, acc[c4 * 4 + 1]);
                acc[c4 * 4 + 2] = fmaf(zk, wv.z, acc[c4 * 4 + 2]);
                acc[c4 * 4 + 3] = fmaf(zk, wv.w, acc[c4 * 4 + 3]);
            }
        }
        const float4* sfsrc = reinterpret_cast<const float4*>(g_sf + (size_t)n * 128 + j * 32);
        #pragma unroll
        for (int c4 = 0; c4 < 8; ++c4) {
            float4 sv = sfsrc[c4];
            float a0 = __fdividef(1.f, 1.f + __expf(-acc[c4 * 4 + 0]));
            float a1 = __fdividef(1.f, 1.f + __expf(-acc[c4 * 4 + 1]));
            float a2 = __fdividef(1.f, 1.f + __expf(-acc[c4 * 4 + 2]));
            float a3 = __fdividef(1.f, 1.f + __expf(-acc[c4 * 4 + 3]));
            fp[c4 * 4 + 0] = fmaf(sv.x, a0, fp[c4 * 4 + 0]);
            fp[c4 * 4 + 1] = fmaf(sv.y, a1, fp[c4 * 4 + 1]);
            fp[c4 * 4 + 2] = fmaf(sv.z, a2, fp[c4 * 4 + 2]);
            fp[c4 * 4 + 3] = fmaf(sv.w, a3, fp[c4 * 4 + 3]);
        }
    }

    // fp -> scratch; fused = fp @ out_fc_W
    #pragma unroll
    for (int c = 0; c < 32; ++c) s_x[c * 256 + tid] = fp[c];
    float fused[64];
    #pragma unroll
    for (int c = 0; c < 64; ++c) fused[c] = 0.f;
    #pragma unroll 1
    for (int k = 0; k < 32; ++k) {
        float fpk = s_x[k * 256 + tid];
        #pragma unroll
        for (int c4 = 0; c4 < 16; ++c4) {
            float4 wv = reinterpret_cast<const float4*>(s_outW)[k * 16 + c4];
            fused[c4 * 4 + 0] = fmaf(fpk, wv.x, fused[c4 * 4 + 0]);
            fused[c4 * 4 + 1] = fmaf(fpk, wv.y, fused[c4 * 4 + 1]);
            fused[c4 * 4 + 2] = fmaf(fpk, wv.z, fused[c4 * 4 + 2]);
            fused[c4 * 4 + 3] = fmaf(fpk, wv.w, fused[c4 * 4 + 3]);
        }
    }

    // fused -> scratch (frees registers), h = relu([reduced, fused] @ lo_W1)
    #pragma unroll
    for (int c = 0; c < 64; ++c) s_x[c * 256 + tid] = fused[c];
    float h[64];
    #pragma unroll
    for (int c = 0; c < 64; ++c) h[c] = 0.f;

    const float4* rsrc = reinterpret_cast<const float4*>(g_reduced + (size_t)n * 64);
    #pragma unroll 1
    for (int k4 = 0; k4 < 16; ++k4) {
        float4 r = rsrc[k4];
        #pragma unroll
        for (int kk = 0; kk < 4; ++kk) {
            float xk = (kk == 0) ? r.x : (kk == 1) ? r.y : (kk == 2) ? r.z : r.w;
            #pragma unroll
            for (int c4 = 0; c4 < 16; ++c4) {
                float4 wv = reinterpret_cast<const float4*>(s_lo1)[(k4 * 4 + kk) * 16 + c4];
                h[c4 * 4 + 0] = fmaf(xk, wv.x, h[c4 * 4 + 0]);
                h[c4 * 4 + 1] = fmaf(xk, wv.y, h[c4 * 4 + 1]);
                h[c4 * 4 + 2] = fmaf(xk, wv.z, h[c4 * 4 + 2]);
                h[c4 * 4 + 3] = fmaf(xk, wv.w, h[c4 * 4 + 3]);
            }
        }
    }
    #pragma unroll 1
    for (int k = 0; k < 64; ++k) {
        float fk = s_x[k * 256 + tid];
        #pragma unroll
        for (int c4 = 0; c4 < 16; ++c4) {
            float4 wv = reinterpret_cast<const float4*>(s_lo1)[(64 + k) * 16 + c4];
            h[c4 * 4 + 0] = fmaf(fk, wv.x, h[c4 * 4 + 0]);
            h[c4 * 4 + 1] = fmaf(fk, wv.y, h[c4 * 4 + 1]);
            h[c4 * 4 + 2] = fmaf(fk, wv.z, h[c4 * 4 + 2]);
            h[c4 * 4 + 3] = fmaf(fk, wv.w, h[c4 * 4 + 3]);
        }
    }
    #pragma unroll
    for (int c = 0; c < 64; ++c) h[c] = fmaxf(h[c], 0.f);

    // h -> scratch, proj = h @ lo_W2 + lo_b2
    #pragma unroll
    for (int c = 0; c < 64; ++c) s_x[c * 256 + tid] = h[c];
    float p[64];
    #pragma unroll
    for (int c = 0; c < 64; ++c) p[c] = s_lob[c];
    #pragma unroll 1
    for (int k = 0; k < 64; ++k) {
        float hk = s_x[k * 256 + tid];
        #pragma unroll
        for (int c4 = 0; c4 < 16; ++c4) {
            float4 wv = reinterpret_cast<const float4*>(s_lo2)[k * 16 + c4];
            p[c4 * 4 + 0] = fmaf(hk, wv.x, p[c4 * 4 + 0]);
            p[c4 * 4 + 1] = fmaf(hk, wv.y, p[c4 * 4 + 1]);
            p[c4 * 4 + 2] = fmaf(hk, wv.z, p[c4 * 4 + 2]);
            p[c4 * 4 + 3] = fmaf(hk, wv.w, p[c4 * 4 + 3]);
        }
    }
    float4* pdst = reinterpret_cast<float4*>(g_proj + (size_t)n * 64);
    #pragma unroll
    for (int c4 = 0; c4 < 16; ++c4)
        pdst[c4] = make_float4(p[c4 * 4 + 0], p[c4 * 4 + 1], p[c4 * 4 + 2], p[c4 * 4 + 3]);
}

// ---------------- k3pre: sentinel-init touched tv segments + flags + lin2 --
__global__ void __launch_bounds__(256) k3pre(const int* __restrict__ bxyz,
                                             float* __restrict__ out)
{
    int w = (blockIdx.x * 256 + threadIdx.x) >> 5;
    int lane = threadIdx.x & 31;
    int4 b = reinterpret_cast<const int4*>(bxyz)[w];
    int lin2 = ((b.x * 16 + b.w) * 180 + b.z) * 240 + b.y;
    if (lane == 0) {
        g_flag[lin2] = 1;
        g_lin2[w] = lin2;
        out[(size_t)NPTS * 64 + (size_t)TVSEG * 64 + w] = (float)lin2;
    }
    if (lane < 16) {
        uint4 s = make_uint4(0xFFFFFFFFu, 0xFFFFFFFFu, 0xFFFFFFFFu, 0xFFFFFFFFu);
        reinterpret_cast<uint4*>(g_tv + (size_t)lin2 * 64)[lane] = s;
    }
}

// ---------------- k3: gather by inv + atomic segment-max -------------------
__device__ __forceinline__ void atomicMaxFloat(float* addr, float v)
{
    if (v >= 0.f) atomicMax((int*)addr, __float_as_int(v));
    else          atomicMin((unsigned int*)addr, __float_as_uint(v));
}

__global__ void __launch_bounds__(256) k3_scatter(const int* __restrict__ inv,
                                                  float* __restrict__ out)
{
    int idx = blockIdx.x * 256 + threadIdx.x;
    int n = idx >> 6, c = idx & 63;
    int src = inv[n];
    float v = g_proj[src * 64 + c];
    out[idx] = v;
    int lin2 = g_lin2[n];
    atomicMaxFloat(&g_tv[(size_t)lin2 * 64 + c], v);
}

// ---------------- k4: finalize tv -> out (flag-gated) ----------------------
__global__ void __launch_bounds__(256) k4_final(float* __restrict__ out)
{
    size_t idx = (size_t)blockIdx.x * 256 + threadIdx.x;   // float4 units
    size_t seg = idx >> 4;
    float4 v = make_float4(0.f, 0.f, 0.f, 0.f);
    if (g_flag[seg])
        v = reinterpret_cast<const float4*>(g_tv)[idx];
    reinterpret_cast<float4*>(out + (size_t)NPTS * 64)[idx] = v;
}

// ---------------- launch ---------------------------------------------------
extern "C" void kernel_launch(void* const* d_in, const int* in_sizes, int n_in,
                              void* d_out, int out_size)
{
    const float* input     = (const float*)d_in[0];
    const int*   coords    = (const int*)  d_in[1];
    const int*   inv       = (const int*)  d_in[2];
    const int*   bxyz      = (const int*)  d_in[3];
    const float* W_red     = (const float*)d_in[4];
    const float* b_red     = (const float*)d_in[5];
    const float* fc_list_W = (const float*)d_in[6];
    const float* fc_list_b = (const float*)d_in[7];
    const float* fcs_W     = (const float*)d_in[8];
    const float* fcs_b     = (const float*)d_in[9];
    const float* fc_W      = (const float*)d_in[10];
    const float* out_fc_W  = (const float*)d_in[11];
    const float* lo_W1     = (const float*)d_in[12];
    const float* lo_W2     = (const float*)d_in[13];
    const float* lo_b2     = (const float*)d_in[14];
    float* out = (float*)d_out;

    void* p;
    cudaGetSymbolAddress(&p, g_flag);
    cudaMemsetAsync(p, 0, TVSEG);

    cudaFuncSetAttribute(k2a_point, cudaFuncAttributeMaxDynamicSharedMemorySize, K2A_SMEM);
    cudaFuncSetAttribute(k2b_point, cudaFuncAttributeMaxDynamicSharedMemorySize, K2B_SMEM);

    k0_zero<<<25000, 256>>>(coords);
    k1_reduce<<<25000, 256>>>(input, W_red, b_red);
    k2a_point<<<782, 256, K2A_SMEM>>>(fc_list_W, fc_list_b, fc_W);
    k2b_point<<<782, 256, K2B_SMEM>>>(fcs_W, fcs_b, out_fc_W, lo_W1, lo_W2, lo_b2);
    k3pre<<<25000, 256>>>(bxyz, out);
    k3_scatter<<<50000, 256>>>(inv, out);
    k4_final<<<86400, 256>>>(out);
}